// round 5
// baseline (speedup 1.0000x reference)
#include <cuda_runtime.h>
#include <cuda_bf16.h>
#include <cstdint>

// Problem constants
#define Bn   32
#define Tn   256
#define Un   128
#define Um1  127
#define Vn   4096
#define ND   383            // number of anti-diagonals (Tn+Un-1)

// ---------------- device scratch ---------------------------------------------
__device__ __align__(16) __nv_bfloat16 g_expE[(size_t)Bn * Tn * Vn]; // exp(E) bf16
__device__ __align__(16) __nv_bfloat16 g_expP[(size_t)Bn * Un * Vn]; // exp(P) bf16
__device__ __align__(16) float gd_blank[(size_t)Bn * ND * 128]; // diag-major blank_lp
__device__ __align__(16) float gd_lab  [(size_t)Bn * ND * 128]; // diag-major lab_lp

// ---------------- PTX helpers ------------------------------------------------
__device__ __forceinline__ uint32_t smem_u32(const void* p) {
    uint32_t a;
    asm("{ .reg .u64 t; cvta.to.shared.u64 t, %1; cvt.u32.u64 %0, t; }"
        : "=r"(a) : "l"(p));
    return a;
}
#define CP16(dst, src)   asm volatile("cp.async.cg.shared.global [%0], [%1], 16;" :: "r"(dst), "l"(src) : "memory")
#define CP_COMMIT()      asm volatile("cp.async.commit_group;" ::: "memory")

#define LDSM4(r0, r1, r2, r3, addr) \
    asm volatile("ldmatrix.sync.aligned.m8n8.x4.shared.b16 {%0,%1,%2,%3}, [%4];" \
        : "=r"(r0), "=r"(r1), "=r"(r2), "=r"(r3) : "r"(addr))

#define MMA16816(c, a, bq) \
    asm volatile("mma.sync.aligned.m16n8k16.row.col.f32.bf16.bf16.f32 " \
        "{%0,%1,%2,%3}, {%4,%5,%6,%7}, {%8,%9}, {%0,%1,%2,%3};" \
        : "+f"((c)[0]), "+f"((c)[1]), "+f"((c)[2]), "+f"((c)[3]) \
        : "r"((a)[0]), "r"((a)[1]), "r"((a)[2]), "r"((a)[3]), \
          "r"((bq)[0]), "r"((bq)[1]))

// ---------------- kernel 1: exp + bf16 convert (no max shift needed) ---------
__global__ void expcvt_kernel(const float* __restrict__ E,
                              const float* __restrict__ P) {
    const size_t NE = (size_t)Bn * Tn * Vn;
    size_t i = ((size_t)blockIdx.x * 256 + threadIdx.x) * 8;
    const float* src;
    __nv_bfloat16* dst;
    if (i < NE) { src = E + i; dst = g_expE + i; }
    else        { src = P + (i - NE); dst = g_expP + (i - NE); }
    float4 v0 = *(const float4*)(src);
    float4 v1 = *(const float4*)(src + 4);
    __nv_bfloat162 o[4];
    o[0] = __floats2bfloat162_rn(__expf(v0.x), __expf(v0.y));
    o[1] = __floats2bfloat162_rn(__expf(v0.z), __expf(v0.w));
    o[2] = __floats2bfloat162_rn(__expf(v1.x), __expf(v1.y));
    o[3] = __floats2bfloat162_rn(__expf(v1.z), __expf(v1.w));
    uint4 pk;
    pk.x = *(uint32_t*)&o[0]; pk.y = *(uint32_t*)&o[1];
    pk.z = *(uint32_t*)&o[2]; pk.w = *(uint32_t*)&o[3];
    *(uint4*)dst = pk;
}

// ---------------- kernel 2: HMMA GEMM + fused epilogue -----------------------
// CTA tile: 64(t) x 64(u); K = 4096 in 32 chunks of BK=128 elems (256B rows).
// 8 warps as 2(m) x 4(n); warp tile 32x16 via mma.m16n8k16.
// smem/stage: A 64x256B + B 64x256B = 32KB; 3 stages; 2 CTAs/SM.
#define SMEM_HDR  1024
#define STAGE_B   32768
#define SMEM_TOT  (SMEM_HDR + 3 * STAGE_B)   // 99328

__global__ __launch_bounds__(256, 2) void gemm_kernel(const float* __restrict__ E,
                                                      const float* __restrict__ P,
                                                      const int* __restrict__ labels) {
    extern __shared__ __align__(1024) char smem[];
    uint32_t sb = smem_u32(smem);
    float* p0s = (float*)(smem);
    float* pls = (float*)(smem + 256);
    int*   lbs = (int*)(smem + 512);

    int tid = threadIdx.x, lane = tid & 31, wid = tid >> 5;
    int wm = wid >> 2;              // 0..1  (m group of 32 rows)
    int wn = wid & 3;               // 0..3  (n group of 16 cols)
    int t0 = blockIdx.x * 64;
    int u0 = blockIdx.y * 64;
    int b  = blockIdx.z;

    // header: p0, p_lab, labels for this CTA's u range
    if (tid < 64) {
        int u = u0 + tid;
        const float* Pr = P + (size_t)(b * Un + u) * Vn;
        p0s[tid] = Pr[0];
        if (u < Um1) {
            int l = labels[b * Um1 + u];
            lbs[tid] = l;
            pls[tid] = Pr[l];
        }
    }

    // cp.async producer: thread -> row r = tid>>2 (0..63), chunks (tid&3)*4+q
    auto issue = [&](int k) {
        uint32_t base = sb + SMEM_HDR + (k % 3) * STAGE_B;
        int r = tid >> 2;
        int c0 = (tid & 3) * 4;
        const __nv_bfloat16* asrc = g_expE + (size_t)(b * Tn + t0 + r) * Vn + k * 128;
        const __nv_bfloat16* bsrc = g_expP + (size_t)(b * Un + u0 + r) * Vn + k * 128;
        uint32_t bb = base + 16384;
#pragma unroll
        for (int q = 0; q < 4; q++) {
            int c = c0 + q;
            uint32_t sw = (uint32_t)(r * 256 + ((c ^ (r & 7)) << 4));
            CP16(base + sw, asrc + c * 8);
            CP16(bb + sw,   bsrc + c * 8);
        }
        CP_COMMIT();
    };

    issue(0); issue(1);

    float cr[2][2][4] = {};

    for (int k = 0; k < 32; k++) {
        if (k < 30) asm volatile("cp.async.wait_group 1;" ::: "memory");
        else        asm volatile("cp.async.wait_group 0;" ::: "memory");
        __syncthreads();
        if (k + 2 < 32) issue(k + 2);

        uint32_t sA = sb + SMEM_HDR + (k % 3) * STAGE_B;
        uint32_t sB = sA + 16384;
#pragma unroll
        for (int kf = 0; kf < 8; kf++) {
            uint32_t afr[2][4], bfr[2][2];
#pragma unroll
            for (int mi = 0; mi < 2; mi++) {
                int row = wm * 32 + mi * 16 + (lane & 15);
                int kc  = kf * 2 + (lane >> 4);
                uint32_t ad = sA + row * 256 + (((uint32_t)(kc ^ (row & 7))) << 4);
                LDSM4(afr[mi][0], afr[mi][1], afr[mi][2], afr[mi][3], ad);
            }
            {
                int g = lane >> 3;
                int nrow = wn * 16 + ((g >> 1) << 3) + (lane & 7);
                int kc   = kf * 2 + (g & 1);
                uint32_t bd = sB + nrow * 256 + (((uint32_t)(kc ^ (nrow & 7))) << 4);
                uint32_t r0, r1, r2, r3;
                LDSM4(r0, r1, r2, r3, bd);
                bfr[0][0] = r0; bfr[0][1] = r1;
                bfr[1][0] = r2; bfr[1][1] = r3;
            }
#pragma unroll
            for (int mi = 0; mi < 2; mi++)
#pragma unroll
                for (int ni = 0; ni < 2; ni++)
                    MMA16816(cr[mi][ni], afr[mi], bfr[ni]);
        }
    }

    // ---- epilogue: ln = log(acc); blank/lab in diagonal-major layout --------
    float* gbd = gd_blank + (size_t)b * ND * 128;
    float* gld = gd_lab   + (size_t)b * ND * 128;
#pragma unroll
    for (int mi = 0; mi < 2; mi++) {
#pragma unroll
        for (int h = 0; h < 2; h++) {
            int t = t0 + wm * 32 + mi * 16 + h * 8 + (lane >> 2);
            const float* Er = E + (size_t)(b * Tn + t) * Vn;
            float e0 = Er[0];
#pragma unroll
            for (int ni = 0; ni < 2; ni++) {
#pragma unroll
                for (int j = 0; j < 2; j++) {
                    int ui = wn * 16 + ni * 8 + (lane & 3) * 2 + j;
                    int u  = u0 + ui;
                    float ln = __logf(cr[mi][ni][h * 2 + j]);
                    gbd[(t + u) * 128 + u] = e0 + p0s[ui] - ln;
                    if (u < Um1)
                        gld[(t + u) * 128 + u] = Er[lbs[ui]] + pls[ui] - ln;
                }
            }
        }
    }
}

// ---------------- kernel 3: register-wavefront DP (1 warp / batch) -----------
// Thread owns u = lane*4 .. lane*4+3; alpha in registers; shfl for u-1 neighbor.
// Diagonal d needs row d-1 of the diag-major operand arrays.
__device__ __forceinline__ float lse_cell(int d, int u, float a_u, float a_um1,
                                          float bvv, float lvv) {
    const float NEG = -1e30f;
    int t = d - u;
    if (t < 0 || t > Tn - 1) return NEG;
    float v = (t >= 1) ? (a_u + bvv) : NEG;
    float h = (u >= 1) ? (a_um1 + lvv) : NEG;
    float m = fmaxf(v, h);
    float z = fminf(v, h) - m;
    return m + __logf(1.0f + __expf(z));
}

__global__ void dp_kernel(const int* __restrict__ ilen,
                          const int* __restrict__ llen,
                          float* __restrict__ out) {
    const float NEG = -1e30f;
    int b = blockIdx.x;
    int lane = threadIdx.x;          // 32
    const float* gb = gd_blank + (size_t)b * ND * 128;
    const float* gl = gd_lab   + (size_t)b * ND * 128;
    int Tl = ilen[b], Ul = llen[b];
    int dfin = Tl - 1 + Ul;
    int u0 = lane * 4;
    bool owner = (u0 <= Ul) && (Ul < u0 + 4);
    float bfin = gb[dfin * 128 + Ul];    // blank_lp[Tl-1, Ul]

    float a0 = (u0 == 0) ? 0.0f : NEG, a1 = NEG, a2 = NEG, a3 = NEG;

    float4 pb[8], pl[8];
#pragma unroll
    for (int s = 0; s < 8; s++) {        // operands for diagonals 1..8 (rows 0..7)
        pb[s] = *(const float4*)&gb[s * 128 + u0];
        pl[s] = *(const float4*)&gl[s * 128 + u0];
    }

    for (int d0 = 1; d0 <= 382; d0 += 8) {
#pragma unroll
        for (int ss = 0; ss < 8; ss++) {
            int d = d0 + ss;
            if (d > 382) break;
            float4 bv = pb[ss], lv = pl[ss];
            int nr = d + 7; if (nr > 381) nr = 381;   // row for diag d+8
            pb[ss] = *(const float4*)&gb[nr * 128 + u0];
            pl[ss] = *(const float4*)&gl[nr * 128 + u0];

            float am1 = __shfl_up_sync(0xffffffffu, a3, 1);   // alpha[u0-1]
            float lm1 = __shfl_up_sync(0xffffffffu, lv.w, 1); // lab[u0-1]

            float n0 = lse_cell(d, u0 + 0, a0, am1, bv.x, lm1);
            float n1 = lse_cell(d, u0 + 1, a1, a0,  bv.y, lv.x);
            float n2 = lse_cell(d, u0 + 2, a2, a1,  bv.z, lv.y);
            float n3 = lse_cell(d, u0 + 3, a3, a2,  bv.w, lv.z);
            a0 = n0; a1 = n1; a2 = n2; a3 = n3;

            if (d == dfin && owner) {
                int j = Ul & 3;
                float av = (j == 0) ? n0 : (j == 1) ? n1 : (j == 2) ? n2 : n3;
                out[b] = -(av + bfin);
            }
        }
    }
}

// ---------------- launcher ---------------------------------------------------
extern "C" void kernel_launch(void* const* d_in, const int* in_sizes, int n_in,
                              void* d_out, int out_size) {
    const float* e      = (const float*)d_in[0];
    const float* p      = (const float*)d_in[1];
    const int*   labels = (const int*)  d_in[2];
    const int*   ilen   = (const int*)  d_in[3];
    const int*   llen   = (const int*)  d_in[4];
    float* out = (float*)d_out;

    cudaFuncSetAttribute(gemm_kernel,
                         cudaFuncAttributeMaxDynamicSharedMemorySize, SMEM_TOT);

    // total elems = B*T*V + B*U*V = 50331648 ; / (256 threads * 8 elems) = 24576
    expcvt_kernel<<<24576, 256>>>(e, p);
    gemm_kernel<<<dim3(4, 2, Bn), 256, SMEM_TOT>>>(e, p, labels);
    dp_kernel<<<Bn, 32>>>(ilen, llen, out);
}

// round 7
// speedup vs baseline: 1.0145x; 1.0145x over previous
#include <cuda_runtime.h>
#include <cuda_bf16.h>
#include <cstdint>

// Problem constants
#define Bn   32
#define Tn   256
#define Un   128
#define Um1  127
#define Vn   4096
#define ND   383            // number of anti-diagonals (Tn+Un-1)

// ---------------- device scratch ---------------------------------------------
__device__ __align__(16) __nv_bfloat16 g_expE[(size_t)Bn * Tn * Vn]; // exp(E) bf16
__device__ __align__(16) __nv_bfloat16 g_expP[(size_t)Bn * Un * Vn]; // exp(P) bf16
__device__ __align__(16) float gd_blank[(size_t)Bn * ND * 128]; // diag-major blank_lp
__device__ __align__(16) float gd_lab  [(size_t)Bn * ND * 128]; // diag-major lab_lp

// ---------------- PTX helpers ------------------------------------------------
__device__ __forceinline__ uint32_t smem_u32(const void* p) {
    uint32_t a;
    asm("{ .reg .u64 t; cvta.to.shared.u64 t, %1; cvt.u32.u64 %0, t; }"
        : "=r"(a) : "l"(p));
    return a;
}
#define CP16(dst, src)   asm volatile("cp.async.cg.shared.global [%0], [%1], 16;" :: "r"(dst), "l"(src) : "memory")
#define CP_COMMIT()      asm volatile("cp.async.commit_group;" ::: "memory")

#define LDSM4(r0, r1, r2, r3, addr) \
    asm volatile("ldmatrix.sync.aligned.m8n8.x4.shared.b16 {%0,%1,%2,%3}, [%4];" \
        : "=r"(r0), "=r"(r1), "=r"(r2), "=r"(r3) : "r"(addr))

#define MMA16816(c, a, bq) \
    asm volatile("mma.sync.aligned.m16n8k16.row.col.f32.bf16.bf16.f32 " \
        "{%0,%1,%2,%3}, {%4,%5,%6,%7}, {%8,%9}, {%0,%1,%2,%3};" \
        : "+f"((c)[0]), "+f"((c)[1]), "+f"((c)[2]), "+f"((c)[3]) \
        : "r"((a)[0]), "r"((a)[1]), "r"((a)[2]), "r"((a)[3]), \
          "r"((bq)[0]), "r"((bq)[1]))

// ---------------- kernel 1: exp + bf16 convert (no max shift needed) ---------
__global__ void expcvt_kernel(const float* __restrict__ E,
                              const float* __restrict__ P) {
    const size_t NE = (size_t)Bn * Tn * Vn;
    size_t i = ((size_t)blockIdx.x * 256 + threadIdx.x) * 8;
    const float* src;
    __nv_bfloat16* dst;
    if (i < NE) { src = E + i; dst = g_expE + i; }
    else        { src = P + (i - NE); dst = g_expP + (i - NE); }
    float4 v0 = *(const float4*)(src);
    float4 v1 = *(const float4*)(src + 4);
    __nv_bfloat162 o[4];
    o[0] = __floats2bfloat162_rn(__expf(v0.x), __expf(v0.y));
    o[1] = __floats2bfloat162_rn(__expf(v0.z), __expf(v0.w));
    o[2] = __floats2bfloat162_rn(__expf(v1.x), __expf(v1.y));
    o[3] = __floats2bfloat162_rn(__expf(v1.z), __expf(v1.w));
    uint4 pk;
    pk.x = *(uint32_t*)&o[0]; pk.y = *(uint32_t*)&o[1];
    pk.z = *(uint32_t*)&o[2]; pk.w = *(uint32_t*)&o[3];
    *(uint4*)dst = pk;
}

// ---------------- kernel 2: HMMA GEMM + staged coalesced epilogue ------------
// CTA tile: 64(t) x 128(u); K = 4096 in 64 chunks of BK=64 (128B rows).
// 8 warps as 2(m) x 4(n); warp tile 32x32 via mma.m16n8k16. (round-4 mainloop)
#define SMEM_HDR  2048
#define STAGE_B   24576
#define SMEM_TOT  (SMEM_HDR + 4 * STAGE_B)   // 100352
#define LNPITCH   130                        // 64 x 130 f32 staging (padded)

__global__ __launch_bounds__(256, 1) void gemm_kernel(const float* __restrict__ E,
                                                      const float* __restrict__ P,
                                                      const int* __restrict__ labels) {
    extern __shared__ __align__(1024) char smem[];
    uint32_t sb = smem_u32(smem);
    float* p0s = (float*)(smem);            // [128]
    float* pls = (float*)(smem + 512);      // [127]
    int*   lbs = (int*)(smem + 1024);       // [127]
    float* e0s = (float*)(smem + 1536);     // [64]
    float* sln = (float*)(smem + SMEM_HDR); // 64 x LNPITCH staging (after mainloop)

    int tid = threadIdx.x, lane = tid & 31, wid = tid >> 5;
    int wm = wid >> 2;              // 0..1  (m group of 32 rows)
    int wn = wid & 3;               // 0..3  (n group of 32 cols)
    int t0 = blockIdx.x * 64;
    int b  = blockIdx.y;

    // header: p0, p_lab, labels, e0 for this batch / t-range
    if (tid < Un) {
        const float* Pr = P + (size_t)(b * Un + tid) * Vn;
        p0s[tid] = Pr[0];
        if (tid < Um1) {
            int l = labels[b * Um1 + tid];
            lbs[tid] = l;
            pls[tid] = Pr[l];
        }
    }
    if (tid < 64) e0s[tid] = E[(size_t)(b * Tn + t0 + tid) * Vn];

    // cp.async producer: thread -> (row = tid>>3 [+32k], chunk = tid&7)
    auto issue = [&](int k) {
        uint32_t base = sb + SMEM_HDR + (k & 3) * STAGE_B;
        int r = tid >> 3, c = tid & 7;
        uint32_t sw = (uint32_t)((c ^ (r & 7)) << 4);
        const __nv_bfloat16* asrc = g_expE + (size_t)(b * Tn + t0 + r) * Vn + k * 64 + c * 8;
        CP16(base + r * 128 + sw,        asrc);
        CP16(base + (r + 32) * 128 + sw, asrc + (size_t)32 * Vn);
        const __nv_bfloat16* bsrc = g_expP + (size_t)(b * Un + r) * Vn + k * 64 + c * 8;
        uint32_t bb = base + 8192;
#pragma unroll
        for (int q = 0; q < 4; q++)
            CP16(bb + (r + q * 32) * 128 + sw, bsrc + (size_t)(q * 32) * Vn);
        CP_COMMIT();
    };

    issue(0); issue(1); issue(2);

    float cr[2][4][4] = {};

    for (int k = 0; k < 64; k++) {
        if (k <= 60) asm volatile("cp.async.wait_group 2;" ::: "memory");
        else         asm volatile("cp.async.wait_group 0;" ::: "memory");
        __syncthreads();
        if (k + 3 < 64) issue(k + 3);

        uint32_t sA = sb + SMEM_HDR + (k & 3) * STAGE_B;
        uint32_t sB = sA + 8192;
#pragma unroll
        for (int kf = 0; kf < 4; kf++) {
            uint32_t afr[2][4], bfr[4][2];
#pragma unroll
            for (int mi = 0; mi < 2; mi++) {
                int row = wm * 32 + mi * 16 + (lane & 15);
                int kc  = kf * 2 + (lane >> 4);
                uint32_t ad = sA + row * 128 + (((uint32_t)(kc ^ (row & 7))) << 4);
                LDSM4(afr[mi][0], afr[mi][1], afr[mi][2], afr[mi][3], ad);
            }
#pragma unroll
            for (int p = 0; p < 2; p++) {
                int g = lane >> 3;
                int nrow = wn * 32 + p * 16 + ((g >> 1) << 3) + (lane & 7);
                int kc   = kf * 2 + (g & 1);
                uint32_t bd = sB + nrow * 128 + (((uint32_t)(kc ^ (nrow & 7))) << 4);
                uint32_t r0, r1, r2, r3;
                LDSM4(r0, r1, r2, r3, bd);
                bfr[p * 2 + 0][0] = r0; bfr[p * 2 + 0][1] = r1;
                bfr[p * 2 + 1][0] = r2; bfr[p * 2 + 1][1] = r3;
            }
#pragma unroll
            for (int mi = 0; mi < 2; mi++)
#pragma unroll
                for (int ni = 0; ni < 4; ni++)
                    MMA16816(cr[mi][ni], afr[mi], bfr[ni]);
        }
    }

    // ---- stage ln = log(acc) into smem (fragment layout -> row major) -------
    __syncthreads();   // all warps done reading pipeline stages
#pragma unroll
    for (int mi = 0; mi < 2; mi++) {
#pragma unroll
        for (int h = 0; h < 2; h++) {
            int tl = wm * 32 + mi * 16 + h * 8 + (lane >> 2);
#pragma unroll
            for (int ni = 0; ni < 4; ni++) {
                int u = wn * 32 + ni * 8 + (lane & 3) * 2;
                float2 v;
                v.x = __logf(cr[mi][ni][h * 2 + 0]);
                v.y = __logf(cr[mi][ni][h * 2 + 1]);
                *(float2*)&sln[tl * LNPITCH + u] = v;
            }
        }
    }
    __syncthreads();

    // ---- cooperative coalesced diag-major writes ----------------------------
    // diagonal row (global) = t0 + dl, dl in [0, 190]; cells u in [dl-63, dl] cap [0,127]
    float* gbd = gd_blank + (size_t)b * ND * 128;
    float* gld = gd_lab   + (size_t)b * ND * 128;
    int sub = tid >> 6;               // 0..3 : diagonal within group of 4
    int ui_off = tid & 63;
    for (int it = 0; it < 48; it++) {
        int dl = it * 4 + sub;
        if (dl > 190) break;
        int ulo = dl - 63; if (ulo < 0) ulo = 0;
        int uhi = dl; if (uhi > 127) uhi = 127;
        int ui = ulo + ui_off;
        if (ui <= uhi) {
            int tl = dl - ui;
            float ln = sln[tl * LNPITCH + ui];
            size_t row = (size_t)(t0 + dl) * 128 + ui;
            gbd[row] = e0s[tl] + p0s[ui] - ln;
            if (ui < Um1) {
                float el = E[(size_t)(b * Tn + t0 + tl) * Vn + lbs[ui]];
                gld[row] = el + pls[ui] - ln;
            }
        }
    }
}

// ---------------- kernel 3: register-wavefront DP (1 warp / batch) -----------
__device__ __forceinline__ float lse_cell(int d, int u, float a_u, float a_um1,
                                          float bvv, float lvv) {
    const float NEG = -1e30f;
    int t = d - u;
    if (t < 0 || t > Tn - 1) return NEG;
    float v = (t >= 1) ? (a_u + bvv) : NEG;
    float h = (u >= 1) ? (a_um1 + lvv) : NEG;
    float m = fmaxf(v, h);
    float z = fminf(v, h) - m;
    return m + __logf(1.0f + __expf(z));
}

__global__ __launch_bounds__(32) void dp_kernel(const int* __restrict__ ilen,
                                                const int* __restrict__ llen,
                                                float* __restrict__ out) {
    const float NEG = -1e30f;
    int b = blockIdx.x;
    int lane = threadIdx.x;          // 32
    const float* gb = gd_blank + (size_t)b * ND * 128;
    const float* gl = gd_lab   + (size_t)b * ND * 128;
    int Tl = ilen[b], Ul = llen[b];
    int dfin = Tl - 1 + Ul;
    int u0 = lane * 4;
    bool owner = (u0 <= Ul) && (Ul < u0 + 4);
    float bfin = gb[dfin * 128 + Ul];    // blank_lp[Tl-1, Ul]

    float a0 = (u0 == 0) ? 0.0f : NEG, a1 = NEG, a2 = NEG, a3 = NEG;

    float4 pb[8], pl[8];
#pragma unroll
    for (int s = 0; s < 8; s++) {        // operands for diagonals 1..8 (rows 0..7)
        pb[s] = *(const float4*)&gb[s * 128 + u0];
        pl[s] = *(const float4*)&gl[s * 128 + u0];
    }

    for (int d0 = 1; d0 <= 382; d0 += 8) {
#pragma unroll
        for (int ss = 0; ss < 8; ss++) {
            int d = d0 + ss;
            if (d > 382) break;
            float4 bv = pb[ss], lv = pl[ss];
            int nr = d + 7; if (nr > 381) nr = 381;   // row for diag d+8
            pb[ss] = *(const float4*)&gb[nr * 128 + u0];
            pl[ss] = *(const float4*)&gl[nr * 128 + u0];

            float am1 = __shfl_up_sync(0xffffffffu, a3, 1);   // alpha[u0-1]
            float lm1 = __shfl_up_sync(0xffffffffu, lv.w, 1); // lab[u0-1]

            float n0 = lse_cell(d, u0 + 0, a0, am1, bv.x, lm1);
            float n1 = lse_cell(d, u0 + 1, a1, a0,  bv.y, lv.x);
            float n2 = lse_cell(d, u0 + 2, a2, a1,  bv.z, lv.y);
            float n3 = lse_cell(d, u0 + 3, a3, a2,  bv.w, lv.z);
            a0 = n0; a1 = n1; a2 = n2; a3 = n3;

            if (d == dfin && owner) {
                int j = Ul & 3;
                float av = (j == 0) ? n0 : (j == 1) ? n1 : (j == 2) ? n2 : n3;
                out[b] = -(av + bfin);
            }
        }
    }
}

// ---------------- launcher ---------------------------------------------------
extern "C" void kernel_launch(void* const* d_in, const int* in_sizes, int n_in,
                              void* d_out, int out_size) {
    const float* e      = (const float*)d_in[0];
    const float* p      = (const float*)d_in[1];
    const int*   labels = (const int*)  d_in[2];
    const int*   ilen   = (const int*)  d_in[3];
    const int*   llen   = (const int*)  d_in[4];
    float* out = (float*)d_out;

    cudaFuncSetAttribute(gemm_kernel,
                         cudaFuncAttributeMaxDynamicSharedMemorySize, SMEM_TOT);

    // total elems = B*T*V + B*U*V = 50331648 ; / (256 threads * 8 elems) = 24576
    expcvt_kernel<<<24576, 256>>>(e, p);
    gemm_kernel<<<dim3(4, Bn), 256, SMEM_TOT>>>(e, p, labels);
    dp_kernel<<<Bn, 32>>>(ilen, llen, out);
}

// round 9
// speedup vs baseline: 1.1032x; 1.0874x over previous
#include <cuda_runtime.h>
#include <cuda_bf16.h>
#include <cstdint>

// Problem constants
#define Bn   32
#define Tn   256
#define Un   128
#define Um1  127
#define Vn   4096
#define ND   383            // number of anti-diagonals (Tn+Un-1)

// ---------------- device scratch ---------------------------------------------
__device__ __align__(16) __nv_bfloat16 g_expE[(size_t)Bn * Tn * Vn]; // exp(E) bf16
__device__ __align__(16) __nv_bfloat16 g_expP[(size_t)Bn * Un * Vn]; // exp(P) bf16
__device__ __align__(16) float gd_blank[(size_t)Bn * ND * 128]; // diag-major blank_lp
__device__ __align__(16) float gd_lab  [(size_t)Bn * ND * 128]; // diag-major lab_lp

// ---------------- PTX helpers ------------------------------------------------
__device__ __forceinline__ uint32_t smem_u32(const void* p) {
    uint32_t a;
    asm("{ .reg .u64 t; cvta.to.shared.u64 t, %1; cvt.u32.u64 %0, t; }"
        : "=r"(a) : "l"(p));
    return a;
}
#define CP16(dst, src)   asm volatile("cp.async.cg.shared.global [%0], [%1], 16;" :: "r"(dst), "l"(src) : "memory")
#define CP_COMMIT()      asm volatile("cp.async.commit_group;" ::: "memory")

#define LDSM4(r0, r1, r2, r3, addr) \
    asm volatile("ldmatrix.sync.aligned.m8n8.x4.shared.b16 {%0,%1,%2,%3}, [%4];" \
        : "=r"(r0), "=r"(r1), "=r"(r2), "=r"(r3) : "r"(addr))

#define MMA16816(c, a, bq) \
    asm volatile("mma.sync.aligned.m16n8k16.row.col.f32.bf16.bf16.f32 " \
        "{%0,%1,%2,%3}, {%4,%5,%6,%7}, {%8,%9}, {%0,%1,%2,%3};" \
        : "+f"((c)[0]), "+f"((c)[1]), "+f"((c)[2]), "+f"((c)[3]) \
        : "r"((a)[0]), "r"((a)[1]), "r"((a)[2]), "r"((a)[3]), \
          "r"((bq)[0]), "r"((bq)[1]))

// ---------------- kernel 1: exp + bf16 convert (no max shift needed) ---------
__global__ void expcvt_kernel(const float* __restrict__ E,
                              const float* __restrict__ P) {
    const size_t NE = (size_t)Bn * Tn * Vn;
    size_t i = ((size_t)blockIdx.x * 256 + threadIdx.x) * 8;
    const float* src;
    __nv_bfloat16* dst;
    if (i < NE) { src = E + i; dst = g_expE + i; }
    else        { src = P + (i - NE); dst = g_expP + (i - NE); }
    float4 v0 = *(const float4*)(src);
    float4 v1 = *(const float4*)(src + 4);
    __nv_bfloat162 o[4];
    o[0] = __floats2bfloat162_rn(__expf(v0.x), __expf(v0.y));
    o[1] = __floats2bfloat162_rn(__expf(v0.z), __expf(v0.w));
    o[2] = __floats2bfloat162_rn(__expf(v1.x), __expf(v1.y));
    o[3] = __floats2bfloat162_rn(__expf(v1.z), __expf(v1.w));
    uint4 pk;
    pk.x = *(uint32_t*)&o[0]; pk.y = *(uint32_t*)&o[1];
    pk.z = *(uint32_t*)&o[2]; pk.w = *(uint32_t*)&o[3];
    *(uint4*)dst = pk;
}

// ---------------- kernel 2: HMMA GEMM, 6-stage pipeline ----------------------
// CTA tile: 64(t) x 128(u); K = 4096 in 64 chunks of BK=64 (128B rows).
// 8 warps as 2(m) x 4(n); warp tile 32x32 via mma.m16n8k16.
// smem/stage: A 64x128B = 8KB, B 128x128B = 16KB -> 24KB; 6 stages, 5 in flight.
#define SMEM_HDR  2048
#define STAGE_B   24576
#define NSTAGE    6
#define SMEM_TOT  (SMEM_HDR + NSTAGE * STAGE_B)   // 149504

__global__ __launch_bounds__(256, 1) void gemm_kernel(const float* __restrict__ E,
                                                      const float* __restrict__ P,
                                                      const int* __restrict__ labels) {
    extern __shared__ __align__(1024) char smem[];
    uint32_t sb = smem_u32(smem);
    float* p0s = (float*)(smem);
    float* pls = (float*)(smem + 512);
    int*   lbs = (int*)(smem + 1024);

    int tid = threadIdx.x, lane = tid & 31, wid = tid >> 5;
    int wm = wid >> 2;              // 0..1  (m group of 32 rows)
    int wn = wid & 3;               // 0..3  (n group of 32 cols)
    int t0 = blockIdx.x * 64;
    int b  = blockIdx.y;

    // header: p0, p_lab, labels for this batch
    if (tid < Un) {
        const float* Pr = P + (size_t)(b * Un + tid) * Vn;
        p0s[tid] = Pr[0];
        if (tid < Um1) {
            int l = labels[b * Um1 + tid];
            lbs[tid] = l;
            pls[tid] = Pr[l];
        }
    }

    // cp.async producer: thread -> (row = tid>>3 [+32k], chunk = tid&7)
    auto issue = [&](int k) {
        uint32_t base = sb + SMEM_HDR + (k % NSTAGE) * STAGE_B;
        int r = tid >> 3, c = tid & 7;
        uint32_t sw = (uint32_t)((c ^ (r & 7)) << 4);
        const __nv_bfloat16* asrc = g_expE + (size_t)(b * Tn + t0 + r) * Vn + k * 64 + c * 8;
        CP16(base + r * 128 + sw,        asrc);
        CP16(base + (r + 32) * 128 + sw, asrc + (size_t)32 * Vn);
        const __nv_bfloat16* bsrc = g_expP + (size_t)(b * Un + r) * Vn + k * 64 + c * 8;
        uint32_t bb = base + 8192;
#pragma unroll
        for (int q = 0; q < 4; q++)
            CP16(bb + (r + q * 32) * 128 + sw, bsrc + (size_t)(q * 32) * Vn);
        CP_COMMIT();
    };

    issue(0); issue(1); issue(2); issue(3); issue(4);

    float cr[2][4][4] = {};

    for (int k = 0; k < 64; k++) {
        // guarantee group k complete: pending groups go up to min(k+4, 63)
        if      (k <= 59) asm volatile("cp.async.wait_group 4;" ::: "memory");
        else if (k == 60) asm volatile("cp.async.wait_group 3;" ::: "memory");
        else if (k == 61) asm volatile("cp.async.wait_group 2;" ::: "memory");
        else if (k == 62) asm volatile("cp.async.wait_group 1;" ::: "memory");
        else              asm volatile("cp.async.wait_group 0;" ::: "memory");
        __syncthreads();
        if (k + 5 < 64) issue(k + 5);

        uint32_t sA = sb + SMEM_HDR + (k % NSTAGE) * STAGE_B;
        uint32_t sB = sA + 8192;
#pragma unroll
        for (int kf = 0; kf < 4; kf++) {
            uint32_t afr[2][4], bfr[4][2];
#pragma unroll
            for (int mi = 0; mi < 2; mi++) {
                int row = wm * 32 + mi * 16 + (lane & 15);
                int kc  = kf * 2 + (lane >> 4);
                uint32_t ad = sA + row * 128 + (((uint32_t)(kc ^ (row & 7))) << 4);
                LDSM4(afr[mi][0], afr[mi][1], afr[mi][2], afr[mi][3], ad);
            }
#pragma unroll
            for (int p = 0; p < 2; p++) {
                int g = lane >> 3;
                int nrow = wn * 32 + p * 16 + ((g >> 1) << 3) + (lane & 7);
                int kc   = kf * 2 + (g & 1);
                uint32_t bd = sB + nrow * 128 + (((uint32_t)(kc ^ (nrow & 7))) << 4);
                uint32_t r0, r1, r2, r3;
                LDSM4(r0, r1, r2, r3, bd);
                bfr[p * 2 + 0][0] = r0; bfr[p * 2 + 0][1] = r1;
                bfr[p * 2 + 1][0] = r2; bfr[p * 2 + 1][1] = r3;
            }
#pragma unroll
            for (int mi = 0; mi < 2; mi++)
#pragma unroll
                for (int ni = 0; ni < 4; ni++)
                    MMA16816(cr[mi][ni], afr[mi], bfr[ni]);
        }
    }

    // ---- epilogue (round-4 style): direct diag-major scattered writes -------
    float* gbd = gd_blank + (size_t)b * ND * 128;
    float* gld = gd_lab   + (size_t)b * ND * 128;
#pragma unroll
    for (int mi = 0; mi < 2; mi++) {
#pragma unroll
        for (int h = 0; h < 2; h++) {
            int t = t0 + wm * 32 + mi * 16 + h * 8 + (lane >> 2);
            const float* Er = E + (size_t)(b * Tn + t) * Vn;
            float e0 = Er[0];
#pragma unroll
            for (int ni = 0; ni < 4; ni++) {
#pragma unroll
                for (int j = 0; j < 2; j++) {
                    int u = wn * 32 + ni * 8 + (lane & 3) * 2 + j;
                    float ln = __logf(cr[mi][ni][h * 2 + j]);
                    gbd[(t + u) * 128 + u] = e0 + p0s[u] - ln;
                    if (u < Um1)
                        gld[(t + u) * 128 + u] = Er[lbs[u]] + pls[u] - ln;
                }
            }
        }
    }
}

// ---------------- kernel 3: register-wavefront DP (1 warp / batch) -----------
__device__ __forceinline__ float lse_cell(int d, int u, float a_u, float a_um1,
                                          float bvv, float lvv) {
    const float NEG = -1e30f;
    int t = d - u;
    if (t < 0 || t > Tn - 1) return NEG;
    float v = (t >= 1) ? (a_u + bvv) : NEG;
    float h = (u >= 1) ? (a_um1 + lvv) : NEG;
    float m = fmaxf(v, h);
    float z = fminf(v, h) - m;
    return m + __logf(1.0f + __expf(z));
}

__global__ __launch_bounds__(32) void dp_kernel(const int* __restrict__ ilen,
                                                const int* __restrict__ llen,
                                                float* __restrict__ out) {
    const float NEG = -1e30f;
    int b = blockIdx.x;
    int lane = threadIdx.x;          // 32
    const float* gb = gd_blank + (size_t)b * ND * 128;
    const float* gl = gd_lab   + (size_t)b * ND * 128;
    int Tl = ilen[b], Ul = llen[b];
    int dfin = Tl - 1 + Ul;
    int u0 = lane * 4;
    bool owner = (u0 <= Ul) && (Ul < u0 + 4);
    float bfin = gb[dfin * 128 + Ul];    // blank_lp[Tl-1, Ul]

    float a0 = (u0 == 0) ? 0.0f : NEG, a1 = NEG, a2 = NEG, a3 = NEG;

    float4 pb[8], pl[8];
#pragma unroll
    for (int s = 0; s < 8; s++) {        // operands for diagonals 1..8 (rows 0..7)
        pb[s] = *(const float4*)&gb[s * 128 + u0];
        pl[s] = *(const float4*)&gl[s * 128 + u0];
    }

    for (int d0 = 1; d0 <= 382; d0 += 8) {
#pragma unroll
        for (int ss = 0; ss < 8; ss++) {
            int d = d0 + ss;
            if (d > 382) break;
            float4 bv = pb[ss], lv = pl[ss];
            int nr = d + 7; if (nr > 381) nr = 381;   // row for diag d+8
            pb[ss] = *(const float4*)&gb[nr * 128 + u0];
            pl[ss] = *(const float4*)&gl[nr * 128 + u0];

            float am1 = __shfl_up_sync(0xffffffffu, a3, 1);   // alpha[u0-1]
            float lm1 = __shfl_up_sync(0xffffffffu, lv.w, 1); // lab[u0-1]

            float n0 = lse_cell(d, u0 + 0, a0, am1, bv.x, lm1);
            float n1 = lse_cell(d, u0 + 1, a1, a0,  bv.y, lv.x);
            float n2 = lse_cell(d, u0 + 2, a2, a1,  bv.z, lv.y);
            float n3 = lse_cell(d, u0 + 3, a3, a2,  bv.w, lv.z);
            a0 = n0; a1 = n1; a2 = n2; a3 = n3;

            if (d == dfin && owner) {
                int j = Ul & 3;
                float av = (j == 0) ? n0 : (j == 1) ? n1 : (j == 2) ? n2 : n3;
                out[b] = -(av + bfin);
            }
        }
    }
}

// ---------------- launcher ---------------------------------------------------
extern "C" void kernel_launch(void* const* d_in, const int* in_sizes, int n_in,
                              void* d_out, int out_size) {
    const float* e      = (const float*)d_in[0];
    const float* p      = (const float*)d_in[1];
    const int*   labels = (const int*)  d_in[2];
    const int*   ilen   = (const int*)  d_in[3];
    const int*   llen   = (const int*)  d_in[4];
    float* out = (float*)d_out;

    cudaFuncSetAttribute(gemm_kernel,
                         cudaFuncAttributeMaxDynamicSharedMemorySize, SMEM_TOT);

    // total elems = B*T*V + B*U*V = 50331648 ; / (256 threads * 8 elems) = 24576
    expcvt_kernel<<<24576, 256>>>(e, p);
    gemm_kernel<<<dim3(4, Bn), 256, SMEM_TOT>>>(e, p, labels);
    dp_kernel<<<Bn, 32>>>(ilen, llen, out);
}